// round 1
// baseline (speedup 1.0000x reference)
#include <cuda_runtime.h>

#define NMAX 100000
#define EMAX 3200000

// ---------------- device scratch (static, no allocation) ----------------
__device__ float g_h [(size_t)NMAX * 64];   // encoder output h
__device__ float g_h3[(size_t)NMAX * 64];   // post-Wf2 features
__device__ int   g_cnt[NMAX];
__device__ int   g_off[NMAX];
__device__ int   g_cur[NMAX];
__device__ int   g_edst[EMAX];
__device__ int   g_is64;

// ---------------- adj dtype detection (int64 vs int32) ----------------
// If adj is int64 (values < 1e5, nonneg), every odd 32-bit word is 0.
__global__ void k_detect(const int* __restrict__ a) {
    if (threadIdx.x == 0 && blockIdx.x == 0) {
        int any = 0;
        #pragma unroll
        for (int i = 1; i < 128; i += 2) any |= a[i];
        g_is64 = (any == 0) ? 1 : 0;
    }
}

__device__ __forceinline__ int read_idx(const void* p, long long i) {
    return g_is64 ? (int)((const long long*)p)[i] : ((const int*)p)[i];
}

// ---------------- zero counts ----------------
__global__ void k_zero(int n) {
    int i = blockIdx.x * blockDim.x + threadIdx.x;
    if (i < n) g_cnt[i] = 0;
}

// ---------------- encoder: h = relu(x@W1+b1)@W2+b2, warp per node ----------------
__global__ __launch_bounds__(256) void k_enc(
    const float* __restrict__ x,
    const float* __restrict__ W1, const float* __restrict__ b1,
    const float* __restrict__ W2, const float* __restrict__ b2, int n)
{
    __shared__ float  sW1[6 * 64];
    __shared__ float2 sW2[64 * 32];
    __shared__ float  sb1[64];
    __shared__ float2 sb2[32];
    __shared__ float  sh[8][64];

    int tid = threadIdx.x;
    for (int i = tid; i < 6 * 64; i += 256) sW1[i] = W1[i];
    for (int i = tid; i < 64 * 32; i += 256) sW2[i] = ((const float2*)W2)[i];
    if (tid < 64) sb1[tid] = b1[tid];
    if (tid < 32) sb2[tid] = ((const float2*)b2)[tid];
    __syncthreads();

    int lane = tid & 31, w = tid >> 5;
    int wg = blockIdx.x * 8 + w, nw = gridDim.x * 8;
    float2* hf2 = (float2*)g_h;

    for (int i = wg; i < n; i += nw) {
        float xv = (lane < 6) ? x[(size_t)i * 6 + lane] : 0.f;
        float h0 = sb1[lane], h1 = sb1[lane + 32];
        #pragma unroll
        for (int k = 0; k < 6; ++k) {
            float xk = __shfl_sync(0xffffffffu, xv, k);
            h0 = fmaf(xk, sW1[k * 64 + lane], h0);
            h1 = fmaf(xk, sW1[k * 64 + lane + 32], h1);
        }
        h0 = fmaxf(h0, 0.f); h1 = fmaxf(h1, 0.f);
        sh[w][lane] = h0; sh[w][lane + 32] = h1;
        __syncwarp();
        float2 o = sb2[lane];
        #pragma unroll
        for (int k = 0; k < 64; ++k) {
            float hk = sh[w][k];
            float2 wv = sW2[k * 32 + lane];
            o.x = fmaf(hk, wv.x, o.x);
            o.y = fmaf(hk, wv.y, o.y);
        }
        hf2[(size_t)i * 32 + lane] = o;   // node i elements (2*lane, 2*lane+1)
        __syncwarp();
    }
}

// ---------------- edge pass 1: degree counts ----------------
__global__ void k_count(const void* __restrict__ adj, int e) {
    long long i = blockIdx.x * (long long)blockDim.x + threadIdx.x;
    long long stride = gridDim.x * (long long)blockDim.x;
    for (; i < e; i += stride) {
        int s = read_idx(adj, i);          // src = adj row 0
        atomicAdd(&g_cnt[s], 1);
    }
}

// ---------------- exclusive scan of counts (single block) ----------------
__global__ __launch_bounds__(1024) void k_scan(int n) {
    __shared__ int s[1024];
    int t = threadIdx.x;
    int chunk = (n + 1023) / 1024;
    int beg = t * chunk, end = min(beg + chunk, n);
    int tot = 0;
    for (int i = beg; i < end; ++i) tot += g_cnt[i];
    s[t] = tot;
    __syncthreads();
    for (int d = 1; d < 1024; d <<= 1) {
        int v = (t >= d) ? s[t - d] : 0;
        __syncthreads();
        s[t] += v;
        __syncthreads();
    }
    int base = (t > 0) ? s[t - 1] : 0;
    for (int i = beg; i < end; ++i) {
        g_off[i] = base;
        g_cur[i] = base;
        base += g_cnt[i];
    }
}

// ---------------- edge pass 2: fill CSR adjacency ----------------
__global__ void k_fill(const void* __restrict__ adj, int e) {
    long long i = blockIdx.x * (long long)blockDim.x + threadIdx.x;
    long long stride = gridDim.x * (long long)blockDim.x;
    for (; i < e; i += stride) {
        int s = read_idx(adj, i);
        int d = read_idx(adj, (long long)e + i);   // dst = adj row 1
        int pos = atomicAdd(&g_cur[s], 1);
        g_edst[pos] = d;
    }
}

// ---------------- aggregate (scatter-mean) + relu(Wf1) + relu(Wf2), warp/node ----------------
__global__ __launch_bounds__(256) void k_agg_mlp(
    const float* __restrict__ Wf1, const float* __restrict__ bf1,
    const float* __restrict__ Wf2, const float* __restrict__ bf2, int n)
{
    __shared__ float2 sWf1[64 * 32], sWf2[64 * 32];
    __shared__ float2 sbf1[32], sbf2[32];
    __shared__ float  sh[8][64];

    int tid = threadIdx.x;
    for (int i = tid; i < 64 * 32; i += 256) {
        sWf1[i] = ((const float2*)Wf1)[i];
        sWf2[i] = ((const float2*)Wf2)[i];
    }
    if (tid < 32) { sbf1[tid] = ((const float2*)bf1)[tid]; sbf2[tid] = ((const float2*)bf2)[tid]; }
    __syncthreads();

    int lane = tid & 31, w = tid >> 5;
    int wg = blockIdx.x * 8 + w, nw = gridDim.x * 8;
    const float2* hf2 = (const float2*)g_h;
    float2* h3f2 = (float2*)g_h3;

    for (int i = wg; i < n; i += nw) {
        int deg = g_cnt[i];
        int start = g_off[i];
        float2 sum = make_float2(0.f, 0.f);

        for (int base = 0; base < deg; base += 32) {
            int e = base + lane;
            int d = (e < deg) ? g_edst[start + e] : 0;
            int m = min(32, deg - base);
            int j = 0;
            for (; j + 4 <= m; j += 4) {
                int d0 = __shfl_sync(0xffffffffu, d, j);
                int d1 = __shfl_sync(0xffffffffu, d, j + 1);
                int d2 = __shfl_sync(0xffffffffu, d, j + 2);
                int d3 = __shfl_sync(0xffffffffu, d, j + 3);
                float2 v0 = hf2[(size_t)d0 * 32 + lane];
                float2 v1 = hf2[(size_t)d1 * 32 + lane];
                float2 v2 = hf2[(size_t)d2 * 32 + lane];
                float2 v3 = hf2[(size_t)d3 * 32 + lane];
                sum.x += (v0.x + v1.x) + (v2.x + v3.x);
                sum.y += (v0.y + v1.y) + (v2.y + v3.y);
            }
            for (; j < m; ++j) {
                int dd = __shfl_sync(0xffffffffu, d, j);
                float2 v = hf2[(size_t)dd * 32 + lane];
                sum.x += v.x; sum.y += v.y;
            }
        }

        float inv = 1.f / fmaxf((float)deg, 1.f);
        float2 hv = hf2[(size_t)i * 32 + lane];
        hv.x = fmaf(sum.x, inv, hv.x);
        hv.y = fmaf(sum.y, inv, hv.y);

        sh[w][2 * lane] = hv.x; sh[w][2 * lane + 1] = hv.y;
        __syncwarp();
        float2 o = sbf1[lane];
        #pragma unroll
        for (int k = 0; k < 64; ++k) {
            float hk = sh[w][k];
            float2 wv = sWf1[k * 32 + lane];
            o.x = fmaf(hk, wv.x, o.x);
            o.y = fmaf(hk, wv.y, o.y);
        }
        o.x = fmaxf(o.x, 0.f); o.y = fmaxf(o.y, 0.f);
        __syncwarp();
        sh[w][2 * lane] = o.x; sh[w][2 * lane + 1] = o.y;
        __syncwarp();
        float2 o2 = sbf2[lane];
        #pragma unroll
        for (int k = 0; k < 64; ++k) {
            float hk = sh[w][k];
            float2 wv = sWf2[k * 32 + lane];
            o2.x = fmaf(hk, wv.x, o2.x);
            o2.y = fmaf(hk, wv.y, o2.y);
        }
        o2.x = fmaxf(o2.x, 0.f); o2.y = fmaxf(o2.y, 0.f);
        h3f2[(size_t)i * 32 + lane] = o2;
        __syncwarp();
    }
}

// ---------------- heads: scores + types, warp per node ----------------
__global__ __launch_bounds__(256) void k_heads(
    const float* __restrict__ Ws1, const float* __restrict__ bs1,
    const float* __restrict__ Ws2, const float* __restrict__ bs2,
    const float* __restrict__ Wt1, const float* __restrict__ bt1,
    const float* __restrict__ Wt2, const float* __restrict__ bt2,
    float* __restrict__ out, int n)
{
    __shared__ float2 sWh[64 * 32];    // columns 0..31 = Ws1, 32..63 = Wt1
    __shared__ float  sbh[64];
    __shared__ float  sWs2[32];
    __shared__ float  sWt2[32 * 4];
    __shared__ float  sh[8][64];

    int tid = threadIdx.x;
    for (int idx = tid; idx < 64 * 64; idx += 256) {
        int k = idx >> 6, j = idx & 63;
        float v = (j < 32) ? Ws1[k * 32 + j] : Wt1[k * 32 + (j - 32)];
        ((float*)sWh)[k * 64 + j] = v;
    }
    if (tid < 64)  sbh[tid] = (tid < 32) ? bs1[tid] : bt1[tid - 32];
    if (tid < 32)  sWs2[tid] = Ws2[tid];
    if (tid < 128) sWt2[tid] = Wt2[tid];
    __syncthreads();

    int lane = tid & 31, w = tid >> 5;
    int wg = blockIdx.x * 8 + w, nw = gridDim.x * 8;
    const float2* h3f2 = (const float2*)g_h3;
    float bs2v = bs2[0];
    float bt20 = bt2[0], bt21 = bt2[1], bt22 = bt2[2], bt23 = bt2[3];

    for (int i = wg; i < n; i += nw) {
        float2 hv = h3f2[(size_t)i * 32 + lane];
        sh[w][2 * lane] = hv.x; sh[w][2 * lane + 1] = hv.y;
        __syncwarp();
        float2 u = make_float2(sbh[2 * lane], sbh[2 * lane + 1]);
        #pragma unroll
        for (int k = 0; k < 64; ++k) {
            float hk = sh[w][k];
            float2 wv = sWh[k * 32 + lane];
            u.x = fmaf(hk, wv.x, u.x);
            u.y = fmaf(hk, wv.y, u.y);
        }
        u.x = fmaxf(u.x, 0.f); u.y = fmaxf(u.y, 0.f);

        float p = 0.f;
        float tx = 0.f, ty = 0.f, tz = 0.f, tw = 0.f;
        if (lane < 16) {
            p = u.x * sWs2[2 * lane] + u.y * sWs2[2 * lane + 1];
        } else {
            int jj = 2 * lane - 32;
            tx = fmaf(u.x, sWt2[jj * 4 + 0], u.y * sWt2[(jj + 1) * 4 + 0]);
            ty = fmaf(u.x, sWt2[jj * 4 + 1], u.y * sWt2[(jj + 1) * 4 + 1]);
            tz = fmaf(u.x, sWt2[jj * 4 + 2], u.y * sWt2[(jj + 1) * 4 + 2]);
            tw = fmaf(u.x, sWt2[jj * 4 + 3], u.y * sWt2[(jj + 1) * 4 + 3]);
        }
        #pragma unroll
        for (int o = 16; o; o >>= 1) {
            p  += __shfl_xor_sync(0xffffffffu, p,  o);
            tx += __shfl_xor_sync(0xffffffffu, tx, o);
            ty += __shfl_xor_sync(0xffffffffu, ty, o);
            tz += __shfl_xor_sync(0xffffffffu, tz, o);
            tw += __shfl_xor_sync(0xffffffffu, tw, o);
        }
        if (lane == 0) {
            out[i] = p + bs2v;
            float4* to = (float4*)(out + n);
            to[i] = make_float4(tx + bt20, ty + bt21, tz + bt22, tw + bt23);
        }
        __syncwarp();
    }
}

// ---------------- launch ----------------
extern "C" void kernel_launch(void* const* d_in, const int* in_sizes, int n_in,
                              void* d_out, int out_size) {
    const float* x   = (const float*)d_in[0];
    const void*  adj = d_in[1];
    const float* W1  = (const float*)d_in[2];
    const float* b1  = (const float*)d_in[3];
    const float* W2  = (const float*)d_in[4];
    const float* b2  = (const float*)d_in[5];
    const float* Wf1 = (const float*)d_in[6];
    const float* bf1 = (const float*)d_in[7];
    const float* Wf2 = (const float*)d_in[8];
    const float* bf2 = (const float*)d_in[9];
    const float* Ws1 = (const float*)d_in[10];
    const float* bs1 = (const float*)d_in[11];
    const float* Ws2 = (const float*)d_in[12];
    const float* bs2 = (const float*)d_in[13];
    const float* Wt1 = (const float*)d_in[14];
    const float* bt1 = (const float*)d_in[15];
    const float* Wt2 = (const float*)d_in[16];
    const float* bt2 = (const float*)d_in[17];

    int n = in_sizes[0] / 6;
    int e = in_sizes[1] / 2;
    float* out = (float*)d_out;

    k_detect<<<1, 32>>>((const int*)adj);
    k_zero<<<(n + 255) / 256, 256>>>(n);
    k_enc<<<1184, 256>>>(x, W1, b1, W2, b2, n);
    k_count<<<2048, 256>>>(adj, e);
    k_scan<<<1, 1024>>>(n);
    k_fill<<<2048, 256>>>(adj, e);
    k_agg_mlp<<<1184, 256>>>(Wf1, bf1, Wf2, bf2, n);
    k_heads<<<1184, 256>>>(Ws1, bs1, Ws2, bs2, Wt1, bt1, Wt2, bt2, out, n);
}